// round 2
// baseline (speedup 1.0000x reference)
#include <cuda_runtime.h>
#include <cuda_bf16.h>

// ---------------------------------------------------------------------------
// Problem constants (fixed by the dataset)
// ---------------------------------------------------------------------------
#define N_NODES 50000
#define D_IN    64
#define HID     128

// ---------------------------------------------------------------------------
// Scratch (no cudaMalloc allowed -> __device__ globals)
// ---------------------------------------------------------------------------
__device__ float d_deg [N_NODES];
__device__ float d_dis [N_NODES];
__device__ float d_agg1[N_NODES * D_IN];
__device__ float d_h1  [N_NODES * HID];
__device__ float d_agg2[N_NODES * HID];
__device__ float d_h2  [N_NODES * HID];
__device__ float d_AB  [N_NODES * 2 * HID];

// ---------------------------------------------------------------------------
// Vector global reduction (sm_90+): one 16B red instead of 4 scalar atomics
// ---------------------------------------------------------------------------
__device__ __forceinline__ void red_add_v4(float* p, float4 v) {
    asm volatile("red.global.add.v4.f32 [%0], {%1, %2, %3, %4};"
                 :: "l"(p), "f"(v.x), "f"(v.y), "f"(v.z), "f"(v.w)
                 : "memory");
}

// ---------------------------------------------------------------------------
// Degree / norm
// ---------------------------------------------------------------------------
__global__ void init_deg_kernel(float* deg, int n) {
    int i = blockIdx.x * blockDim.x + threadIdx.x;
    if (i < n) deg[i] = 1.0f;               // self loop
}

__global__ void accum_deg_kernel(const int* __restrict__ row, float* deg, int E) {
    int e = blockIdx.x * blockDim.x + threadIdx.x;
    if (e < E) atomicAdd(&deg[row[e]], 1.0f);
}

__global__ void compute_dis_kernel(const float* __restrict__ deg, float* dis, int n) {
    int i = blockIdx.x * blockDim.x + threadIdx.x;
    if (i < n) dis[i] = rsqrtf(deg[i]);
}

// ---------------------------------------------------------------------------
// Conv1 aggregation: agg1 (N x 64), self loops init + edge scatter (16 float4/edge)
// ---------------------------------------------------------------------------
__global__ void init_agg1_kernel(const float* __restrict__ x,
                                 const float* __restrict__ dis,
                                 float* __restrict__ agg1, int n) {
    int gid = blockIdx.x * blockDim.x + threadIdx.x;
    if (gid >= n * (D_IN / 4)) return;
    int node = gid >> 4;                    // 16 float4 per node
    float s = dis[node]; s *= s;
    float4 v = ((const float4*)x)[gid];
    ((float4*)agg1)[gid] = make_float4(v.x * s, v.y * s, v.z * s, v.w * s);
}

__global__ void scatter1_kernel(const float* __restrict__ x,
                                const int* __restrict__ row,
                                const int* __restrict__ col,
                                const float* __restrict__ dis,
                                float* __restrict__ agg1, int E) {
    int gid = blockIdx.x * blockDim.x + threadIdx.x;
    int e = gid >> 4;
    int c = gid & 15;
    if (e >= E) return;
    int r = row[e];
    int d = col[e];
    float nrm = dis[r] * dis[d];
    float4 v = ((const float4*)x)[r * 16 + c];
    v.x *= nrm; v.y *= nrm; v.z *= nrm; v.w *= nrm;
    red_add_v4(&agg1[(d * 16 + c) * 4], v);
}

// ---------------------------------------------------------------------------
// Conv2 aggregation: agg2 (N x 128), edge scatter (32 float4/edge)
// (self-loop init is fused into the GEMM1 epilogue)
// ---------------------------------------------------------------------------
__global__ void scatter2_kernel(const float* __restrict__ h1,
                                const int* __restrict__ row,
                                const int* __restrict__ col,
                                const float* __restrict__ dis,
                                float* __restrict__ agg2, int E) {
    int gid = blockIdx.x * blockDim.x + threadIdx.x;
    int e = gid >> 5;
    int c = gid & 31;
    if (e >= E) return;
    int r = row[e];
    int d = col[e];
    float nrm = dis[r] * dis[d];
    float4 v = ((const float4*)h1)[r * 32 + c];
    v.x *= nrm; v.y *= nrm; v.z *= nrm; v.w *= nrm;
    red_add_v4(&agg2[(d * 32 + c) * 4], v);
}

// ---------------------------------------------------------------------------
// SGEMM: C[M,128] = A[M,K] @ W[K,128] (+bias, +relu), optional fused
//        agg2 init (agg2[m] = C[m] * dis[m]^2).
// BM=64, BK=32, 256 threads, 8x4 register tile per thread.
// ---------------------------------------------------------------------------
template<int K, bool RELU, bool BIAS, bool FUSE>
__global__ void __launch_bounds__(256)
gemm128_kernel(const float* __restrict__ A, const float* __restrict__ W,
               const float* __restrict__ bias, float* __restrict__ C,
               int M, int ldc, int coff,
               const float* __restrict__ dis, float* __restrict__ agg) {
    constexpr int BM = 64, BK = 32, NOUT = 128;
    __shared__ float sA[BM * BK];
    __shared__ float sW[BK * NOUT];

    const int tid = threadIdx.x;        // 256
    const int tx  = tid & 31;           // feature quad (4 consecutive outputs)
    const int ty  = tid >> 5;           // node group (8 nodes each)
    const int m0  = blockIdx.x * BM;

    float acc[8][4];
#pragma unroll
    for (int m = 0; m < 8; m++)
#pragma unroll
        for (int c = 0; c < 4; c++) acc[m][c] = 0.0f;

    for (int k0 = 0; k0 < K; k0 += BK) {
        // load A tile: 64x32 floats = 512 float4, 2 per thread
#pragma unroll
        for (int j = 0; j < 2; j++) {
            int i  = tid + j * 256;     // 0..511
            int r  = i >> 3;
            int c4 = i & 7;
            float4 v = make_float4(0.f, 0.f, 0.f, 0.f);
            int mm = m0 + r;
            if (mm < M) v = *(const float4*)&A[mm * K + k0 + c4 * 4];
            *(float4*)&sA[r * BK + c4 * 4] = v;
        }
        // load W tile: 32x128 floats = 1024 float4, 4 per thread
#pragma unroll
        for (int j = 0; j < 4; j++) {
            int i  = tid + j * 256;     // 0..1023
            int r  = i >> 5;
            int c4 = i & 31;
            *(float4*)&sW[r * NOUT + c4 * 4] =
                *(const float4*)&W[(k0 + r) * NOUT + c4 * 4];
        }
        __syncthreads();

#pragma unroll
        for (int kk = 0; kk < BK; kk += 4) {
            float4 wv[4];
#pragma unroll
            for (int u = 0; u < 4; u++)
                wv[u] = *(const float4*)&sW[(kk + u) * NOUT + tx * 4];
            const float* wp = (const float*)wv;   // wp[u*4 + c]
#pragma unroll
            for (int m = 0; m < 8; m++) {
                float4 av = *(const float4*)&sA[(ty * 8 + m) * BK + kk];
                float a[4] = {av.x, av.y, av.z, av.w};
#pragma unroll
                for (int u = 0; u < 4; u++)
#pragma unroll
                    for (int c = 0; c < 4; c++)
                        acc[m][c] = fmaf(a[u], wp[u * 4 + c], acc[m][c]);
            }
        }
        __syncthreads();
    }

    // epilogue
#pragma unroll
    for (int m = 0; m < 8; m++) {
        int mm = m0 + ty * 8 + m;
        if (mm >= M) continue;
        int j0 = tx * 4;
        float4 r;
        float* rp = &r.x;
#pragma unroll
        for (int c = 0; c < 4; c++) {
            float v = acc[m][c];
            if (BIAS) v += bias[j0 + c];
            if (RELU) v = fmaxf(v, 0.0f);
            rp[c] = v;
        }
        *(float4*)&C[mm * ldc + coff + j0] = r;
        if (FUSE) {
            float s = dis[mm]; s *= s;
            *(float4*)&agg[mm * NOUT + j0] =
                make_float4(r.x * s, r.y * s, r.z * s, r.w * s);
        }
    }
}

// ---------------------------------------------------------------------------
// Per-query predictor: out[q] = relu(A[src] + B[dst] + bc1) . Wc2 + bc2
// One warp per query, 4 features (float4) per lane.
// ---------------------------------------------------------------------------
__global__ void predict_kernel(const float* __restrict__ AB,
                               const int* __restrict__ src,
                               const int* __restrict__ dst,
                               const float* __restrict__ bc1,
                               const float* __restrict__ Wc2,
                               const float* __restrict__ bc2,
                               float* __restrict__ out, int Q) {
    int gid  = blockIdx.x * blockDim.x + threadIdx.x;
    int q    = gid >> 5;
    int lane = gid & 31;
    if (q >= Q) return;
    int s = src[q];
    int d = dst[q];
    const float4* ab4 = (const float4*)AB;   // 64 float4 per node row
    float4 a = ab4[(size_t)s * 64 + lane];          // A part: first 32 float4
    float4 b = ab4[(size_t)d * 64 + 32 + lane];     // B part: last 32 float4
    float4 c = ((const float4*)bc1)[lane];
    float4 w = ((const float4*)Wc2)[lane];
    float v0 = fmaxf(a.x + b.x + c.x, 0.0f);
    float v1 = fmaxf(a.y + b.y + c.y, 0.0f);
    float v2 = fmaxf(a.z + b.z + c.z, 0.0f);
    float v3 = fmaxf(a.w + b.w + c.w, 0.0f);
    float acc = v0 * w.x + v1 * w.y + v2 * w.z + v3 * w.w;
#pragma unroll
    for (int o = 16; o > 0; o >>= 1)
        acc += __shfl_down_sync(0xffffffffu, acc, o);
    if (lane == 0) out[q] = acc + bc2[0];
}

// ---------------------------------------------------------------------------
// Launch
// ---------------------------------------------------------------------------
extern "C" void kernel_launch(void* const* d_in, const int* in_sizes, int n_in,
                              void* d_out, int out_size) {
    const float* x   = (const float*)d_in[0];
    const int*   ei  = (const int*)  d_in[1];
    const int*   eli = (const int*)  d_in[2];
    const float* W1  = (const float*)d_in[3];
    const float* b1  = (const float*)d_in[4];
    const float* W2  = (const float*)d_in[5];
    const float* b2  = (const float*)d_in[6];
    const float* Wc1 = (const float*)d_in[7];
    const float* bc1 = (const float*)d_in[8];
    const float* Wc2 = (const float*)d_in[9];
    const float* bc2 = (const float*)d_in[10];
    float* out = (float*)d_out;

    const int N = in_sizes[0] / D_IN;
    const int E = in_sizes[1] / 2;
    const int Q = in_sizes[2] / 2;
    const int* row = ei;
    const int* col = ei + E;
    const int* src = eli;
    const int* dst = eli + Q;

    float *deg, *dis, *agg1, *h1, *agg2, *h2, *AB;
    cudaGetSymbolAddress((void**)&deg,  d_deg);
    cudaGetSymbolAddress((void**)&dis,  d_dis);
    cudaGetSymbolAddress((void**)&agg1, d_agg1);
    cudaGetSymbolAddress((void**)&h1,   d_h1);
    cudaGetSymbolAddress((void**)&agg2, d_agg2);
    cudaGetSymbolAddress((void**)&h2,   d_h2);
    cudaGetSymbolAddress((void**)&AB,   d_AB);

    const int T = 256;

    // 1. degrees + symmetric norm
    init_deg_kernel   <<<(N + T - 1) / T, T>>>(deg, N);
    accum_deg_kernel  <<<(E + T - 1) / T, T>>>(row, deg, E);
    compute_dis_kernel<<<(N + T - 1) / T, T>>>(deg, dis, N);

    // 2. conv1 aggregation (feature space d=64)
    init_agg1_kernel<<<(N * 16 + T - 1) / T, T>>>(x, dis, agg1, N);
    scatter1_kernel <<<(E * 16 + T - 1) / T, T>>>(x, row, col, dis, agg1, E);

    // 3. h1 = relu(agg1@W1+b1); fused: agg2 = h1 * dis^2 (self loops)
    int gblk = (N + 63) / 64;
    gemm128_kernel<D_IN, true, true, true><<<gblk, 256>>>(
        agg1, W1, b1, h1, N, HID, 0, dis, agg2);

    // 4. conv2 aggregation (feature space h=128)
    scatter2_kernel<<<(E * 32 + T - 1) / T, T>>>(h1, row, col, dis, agg2, E);

    // 5. h2 = agg2@W2 + b2
    gemm128_kernel<HID, false, true, false><<<gblk, 256>>>(
        agg2, W2, b2, h2, N, HID, 0, nullptr, nullptr);

    // 6. AB[n] = [ h2[n]@Wc1_top | h2[n]@Wc1_bot ]  (classifier pushed to nodes)
    gemm128_kernel<HID, false, false, false><<<gblk, 256>>>(
        h2, Wc1, nullptr, AB, N, 2 * HID, 0, nullptr, nullptr);
    gemm128_kernel<HID, false, false, false><<<gblk, 256>>>(
        h2, Wc1 + HID * HID, nullptr, AB, N, 2 * HID, HID, nullptr, nullptr);

    // 7. per-query: relu(A[src]+B[dst]+bc1) . Wc2 + bc2
    predict_kernel<<<(Q * 32 + T - 1) / T, T>>>(
        AB, src, dst, bc1, Wc2, bc2, out, Q);
}

// round 3
// speedup vs baseline: 1.0715x; 1.0715x over previous
#include <cuda_runtime.h>
#include <cuda_bf16.h>
#include <cstdint>

// ---------------------------------------------------------------------------
// Problem constants (fixed by the dataset)
// ---------------------------------------------------------------------------
#define N_NODES 50000
#define D_IN    64
#define HID     128

// ---------------------------------------------------------------------------
// Scratch (no cudaMalloc allowed -> __device__ globals)
// ---------------------------------------------------------------------------
__device__ float d_deg [N_NODES];
__device__ float d_dis [N_NODES];
__device__ float d_agg1[N_NODES * D_IN];
__device__ float d_h1  [N_NODES * HID];
__device__ float d_agg2[N_NODES * HID];
__device__ float d_AB  [N_NODES * 2 * HID];
__device__ float d_Wf  [HID * 2 * HID];   // fused W2 @ [Wc1_top | Wc1_bot]
__device__ float d_bf  [2 * HID];         // fused b2 @ Wc1 (+ bc1 in a-half)

// ---------------------------------------------------------------------------
// PTX helpers
// ---------------------------------------------------------------------------
__device__ __forceinline__ void red_add_v4(float* p, float4 v) {
    asm volatile("red.global.add.v4.f32 [%0], {%1, %2, %3, %4};"
                 :: "l"(p), "f"(v.x), "f"(v.y), "f"(v.z), "f"(v.w)
                 : "memory");
}

__device__ __forceinline__ uint32_t f2tf32(float x) {
    uint32_t r;
    asm("cvt.rna.tf32.f32 %0, %1;" : "=r"(r) : "f"(x));
    return r;
}

__device__ __forceinline__ void mma_tf32(float* c, const uint32_t* a, const uint32_t* b) {
    asm volatile(
        "mma.sync.aligned.m16n8k8.row.col.f32.tf32.tf32.f32 "
        "{%0,%1,%2,%3}, {%4,%5,%6,%7}, {%8,%9}, {%0,%1,%2,%3};"
        : "+f"(c[0]), "+f"(c[1]), "+f"(c[2]), "+f"(c[3])
        : "r"(a[0]), "r"(a[1]), "r"(a[2]), "r"(a[3]), "r"(b[0]), "r"(b[1]));
}

// ---------------------------------------------------------------------------
// Degree / norm
// ---------------------------------------------------------------------------
__global__ void init_deg_kernel(float* deg, int n) {
    int i = blockIdx.x * blockDim.x + threadIdx.x;
    if (i < n) deg[i] = 1.0f;               // self loop
}

__global__ void accum_deg_kernel(const int* __restrict__ row, float* deg, int E) {
    int e = blockIdx.x * blockDim.x + threadIdx.x;
    if (e < E) atomicAdd(&deg[row[e]], 1.0f);
}

__global__ void compute_dis_kernel(const float* __restrict__ deg, float* dis, int n) {
    int i = blockIdx.x * blockDim.x + threadIdx.x;
    if (i < n) dis[i] = rsqrtf(deg[i]);
}

// ---------------------------------------------------------------------------
// Weight fusion: Wf[k][j] = sum_t W2[k][t] * Wc1[(j<128 ? t : 128+t)][j%128]
// (classifier first layer folded through conv2's linear transform)
// ---------------------------------------------------------------------------
__global__ void fuse_weights_kernel(const float* __restrict__ W2,
                                    const float* __restrict__ Wc1,
                                    float* __restrict__ Wf) {
    __shared__ float sw[HID];
    int k = blockIdx.x;         // 0..127
    int j = threadIdx.x;        // 0..255
    if (j < HID) sw[j] = W2[k * HID + j];
    __syncthreads();
    const float* wc = Wc1 + (j >> 7) * HID * HID + (j & 127);
    float acc = 0.0f;
#pragma unroll 8
    for (int t = 0; t < HID; t++) acc = fmaf(sw[t], wc[t * HID], acc);
    Wf[k * (2 * HID) + j] = acc;
}

__global__ void fuse_bias_kernel(const float* __restrict__ b2,
                                 const float* __restrict__ Wc1,
                                 const float* __restrict__ bc1,
                                 float* __restrict__ bf) {
    int j = threadIdx.x;        // 0..255
    const float* wc = Wc1 + (j >> 7) * HID * HID + (j & 127);
    float acc = (j < HID) ? bc1[j] : 0.0f;   // bc1 folded into the a-half
#pragma unroll 8
    for (int t = 0; t < HID; t++) acc = fmaf(b2[t], wc[t * HID], acc);
    bf[j] = acc;
}

// ---------------------------------------------------------------------------
// Conv1 aggregation: agg1 (N x 64), self loops init + edge scatter
// ---------------------------------------------------------------------------
__global__ void init_agg1_kernel(const float* __restrict__ x,
                                 const float* __restrict__ dis,
                                 float* __restrict__ agg1, int n) {
    int gid = blockIdx.x * blockDim.x + threadIdx.x;
    if (gid >= n * (D_IN / 4)) return;
    int node = gid >> 4;                    // 16 float4 per node
    float s = dis[node]; s *= s;
    float4 v = ((const float4*)x)[gid];
    ((float4*)agg1)[gid] = make_float4(v.x * s, v.y * s, v.z * s, v.w * s);
}

__global__ void scatter1_kernel(const float* __restrict__ x,
                                const int* __restrict__ row,
                                const int* __restrict__ col,
                                const float* __restrict__ dis,
                                float* __restrict__ agg1, int E) {
    int gid = blockIdx.x * blockDim.x + threadIdx.x;
    int e = gid >> 4;
    int c = gid & 15;
    if (e >= E) return;
    int r = row[e];
    int d = col[e];
    float nrm = dis[r] * dis[d];
    float4 v = ((const float4*)x)[r * 16 + c];
    v.x *= nrm; v.y *= nrm; v.z *= nrm; v.w *= nrm;
    red_add_v4(&agg1[(d * 16 + c) * 4], v);
}

__global__ void scatter2_kernel(const float* __restrict__ h1,
                                const int* __restrict__ row,
                                const int* __restrict__ col,
                                const float* __restrict__ dis,
                                float* __restrict__ agg2, int E) {
    int gid = blockIdx.x * blockDim.x + threadIdx.x;
    int e = gid >> 5;
    int c = gid & 31;
    if (e >= E) return;
    int r = row[e];
    int d = col[e];
    float nrm = dis[r] * dis[d];
    float4 v = ((const float4*)h1)[r * 32 + c];
    v.x *= nrm; v.y *= nrm; v.z *= nrm; v.w *= nrm;
    red_add_v4(&agg2[(d * 32 + c) * 4], v);
}

// ---------------------------------------------------------------------------
// TF32 tensor-core GEMM: C[M,NOUT] = A[M,K] @ W[K,NOUT] + bias (+relu)
// Optional fused agg2 init (agg[m] = C[m] * dis[m]^2) — NOUT==128 only.
//
// BM=128, per-block N tile = 128 (blockIdx.y picks the N half for NOUT=256),
// BK=32, 256 threads = 8 warps in a 4(M)x2(N) grid; warp tile 32x64 via
// m16n8k8 tf32 mma. Smem holds operands in *fragment-major* order so every
// fragment fetch is one conflict-free LDS.128 (A) / LDS.64 (B).
// ---------------------------------------------------------------------------
template<int K, int NOUT, bool RELU, bool FUSE>
__global__ void __launch_bounds__(256, 2)
mma_gemm_kernel(const float* __restrict__ A, const float* __restrict__ W,
                const float* __restrict__ bias, float* __restrict__ C,
                int M, const float* __restrict__ dis, float* __restrict__ agg) {
    constexpr int BM = 128, BK = 32;
    __shared__ uint32_t sA[4 * 8 * 32 * 4];   // [kt][mt][lane][reg]  16KB
    __shared__ uint32_t sB[4 * 16 * 32 * 2];  // [kt][nt][lane][reg]  16KB

    const int tid  = threadIdx.x;
    const int m0   = blockIdx.x * BM;
    const int n0   = blockIdx.y * 128;
    const int w    = tid >> 5, lane = tid & 31;
    const int wm   = (w & 3) * 32, wn = (w >> 2) * 64;
    const int g    = lane >> 2, tg = lane & 3;

    float acc[2][8][4];
#pragma unroll
    for (int m = 0; m < 2; m++)
#pragma unroll
        for (int n = 0; n < 8; n++)
#pragma unroll
            for (int c = 0; c < 4; c++) acc[m][n][c] = 0.0f;

    for (int k0 = 0; k0 < K; k0 += BK) {
        // --- A tile: 128x32 floats, permuted to mma-fragment order ---
#pragma unroll
        for (int j = 0; j < 4; j++) {
            int i  = tid + j * 256;          // 0..1023 float4 slots
            int r  = i >> 3, c4 = i & 7;
            int mm = m0 + r;
            float4 v = make_float4(0.f, 0.f, 0.f, 0.f);
            if (mm < M) v = *(const float4*)&A[(size_t)mm * K + k0 + c4 * 4];
            int kt = c4 >> 1, chalf = c4 & 1;
            int mt = r >> 4, rp = r & 15;
            int rlow = rp & 7, rhigh = rp >> 3;
            int reg = chalf * 2 + rhigh;
            uint32_t* p = &sA[((kt * 8 + mt) * 32 + rlow * 4) * 4 + reg];
            p[0]  = f2tf32(v.x);
            p[4]  = f2tf32(v.y);
            p[8]  = f2tf32(v.z);
            p[12] = f2tf32(v.w);
        }
        // --- B tile: 32x128 floats, permuted to mma-fragment order ---
#pragma unroll
        for (int j = 0; j < 4; j++) {
            int i  = tid + j * 256;
            int kr = i >> 5, n4 = i & 31;
            float4 v = *(const float4*)&W[(size_t)(k0 + kr) * NOUT + n0 + n4 * 4];
            int kt = kr >> 3, kp = kr & 7;
            int tig = kp & 3, khigh = kp >> 2;
            int nt = n4 >> 1, nlow = (n4 & 1) * 4;
            uint32_t* p = &sB[((kt * 16 + nt) * 32 + nlow * 4 + tig) * 2 + khigh];
            p[0]  = f2tf32(v.x);
            p[8]  = f2tf32(v.y);
            p[16] = f2tf32(v.z);
            p[24] = f2tf32(v.w);
        }
        __syncthreads();

#pragma unroll
        for (int kt = 0; kt < 4; kt++) {
            uint4 af[2];
            uint2 bf[8];
#pragma unroll
            for (int mt2 = 0; mt2 < 2; mt2++)
                af[mt2] = *(const uint4*)&sA[((kt * 8 + (wm >> 4) + mt2) * 32 + lane) * 4];
#pragma unroll
            for (int nt2 = 0; nt2 < 8; nt2++)
                bf[nt2] = *(const uint2*)&sB[((kt * 16 + (wn >> 3) + nt2) * 32 + lane) * 2];
#pragma unroll
            for (int mt2 = 0; mt2 < 2; mt2++)
#pragma unroll
                for (int nt2 = 0; nt2 < 8; nt2++)
                    mma_tf32(acc[mt2][nt2],
                             (const uint32_t*)&af[mt2],
                             (const uint32_t*)&bf[nt2]);
        }
        __syncthreads();
    }

    // --- epilogue ---
#pragma unroll
    for (int mt2 = 0; mt2 < 2; mt2++) {
        int r0 = m0 + wm + mt2 * 16 + g;
#pragma unroll
        for (int h = 0; h < 2; h++) {
            int r = r0 + h * 8;
            if (r >= M) continue;
            float s = 0.0f;
            if (FUSE) { s = dis[r]; s *= s; }
#pragma unroll
            for (int nt2 = 0; nt2 < 8; nt2++) {
                int col = n0 + wn + nt2 * 8 + tg * 2;
                float v0 = acc[mt2][nt2][h * 2 + 0] + bias[col];
                float v1 = acc[mt2][nt2][h * 2 + 1] + bias[col + 1];
                if (RELU) { v0 = fmaxf(v0, 0.f); v1 = fmaxf(v1, 0.f); }
                *(float2*)&C[(size_t)r * NOUT + col] = make_float2(v0, v1);
                if (FUSE)
                    *(float2*)&agg[(size_t)r * 128 + col] = make_float2(v0 * s, v1 * s);
            }
        }
    }
}

// ---------------------------------------------------------------------------
// Per-query predictor: out[q] = relu(A[src] + B[dst]) . Wc2 + bc2
// (bc1 is already folded into the a-half of AB's bias)
// ---------------------------------------------------------------------------
__global__ void predict_kernel(const float* __restrict__ AB,
                               const int* __restrict__ src,
                               const int* __restrict__ dst,
                               const float* __restrict__ Wc2,
                               const float* __restrict__ bc2,
                               float* __restrict__ out, int Q) {
    int gid  = blockIdx.x * blockDim.x + threadIdx.x;
    int q    = gid >> 5;
    int lane = gid & 31;
    if (q >= Q) return;
    int s = src[q];
    int d = dst[q];
    const float4* ab4 = (const float4*)AB;           // 64 float4 per node row
    float4 a = ab4[(size_t)s * 64 + lane];           // a-part: first 32 float4
    float4 b = ab4[(size_t)d * 64 + 32 + lane];      // b-part: last 32 float4
    float4 w = ((const float4*)Wc2)[lane];
    float v0 = fmaxf(a.x + b.x, 0.0f);
    float v1 = fmaxf(a.y + b.y, 0.0f);
    float v2 = fmaxf(a.z + b.z, 0.0f);
    float v3 = fmaxf(a.w + b.w, 0.0f);
    float acc = v0 * w.x + v1 * w.y + v2 * w.z + v3 * w.w;
#pragma unroll
    for (int o = 16; o > 0; o >>= 1)
        acc += __shfl_down_sync(0xffffffffu, acc, o);
    if (lane == 0) out[q] = acc + bc2[0];
}

// ---------------------------------------------------------------------------
// Launch
// ---------------------------------------------------------------------------
extern "C" void kernel_launch(void* const* d_in, const int* in_sizes, int n_in,
                              void* d_out, int out_size) {
    const float* x   = (const float*)d_in[0];
    const int*   ei  = (const int*)  d_in[1];
    const int*   eli = (const int*)  d_in[2];
    const float* W1  = (const float*)d_in[3];
    const float* b1  = (const float*)d_in[4];
    const float* W2  = (const float*)d_in[5];
    const float* b2  = (const float*)d_in[6];
    const float* Wc1 = (const float*)d_in[7];
    const float* bc1 = (const float*)d_in[8];
    const float* Wc2 = (const float*)d_in[9];
    const float* bc2 = (const float*)d_in[10];
    float* out = (float*)d_out;

    const int N = in_sizes[0] / D_IN;
    const int E = in_sizes[1] / 2;
    const int Q = in_sizes[2] / 2;
    const int* row = ei;
    const int* col = ei + E;
    const int* src = eli;
    const int* dst = eli + Q;

    float *deg, *dis, *agg1, *h1, *agg2, *AB, *Wf, *bf;
    cudaGetSymbolAddress((void**)&deg,  d_deg);
    cudaGetSymbolAddress((void**)&dis,  d_dis);
    cudaGetSymbolAddress((void**)&agg1, d_agg1);
    cudaGetSymbolAddress((void**)&h1,   d_h1);
    cudaGetSymbolAddress((void**)&agg2, d_agg2);
    cudaGetSymbolAddress((void**)&AB,   d_AB);
    cudaGetSymbolAddress((void**)&Wf,   d_Wf);
    cudaGetSymbolAddress((void**)&bf,   d_bf);

    const int T = 256;

    // 1. degrees + symmetric norm
    init_deg_kernel   <<<(N + T - 1) / T, T>>>(deg, N);
    accum_deg_kernel  <<<(E + T - 1) / T, T>>>(row, deg, E);
    compute_dis_kernel<<<(N + T - 1) / T, T>>>(deg, dis, N);

    // 2. fuse classifier layer through conv2's linear transform
    fuse_weights_kernel<<<HID, 256>>>(W2, Wc1, Wf);
    fuse_bias_kernel   <<<1, 256>>>(b2, Wc1, bc1, bf);

    // 3. conv1 aggregation (feature space d=64)
    init_agg1_kernel<<<(N * 16 + T - 1) / T, T>>>(x, dis, agg1, N);
    scatter1_kernel <<<(E * 16 + T - 1) / T, T>>>(x, row, col, dis, agg1, E);

    // 4. h1 = relu(agg1@W1+b1); fused: agg2 = h1 * dis^2 (self loops)
    int gblk = (N + 127) / 128;
    mma_gemm_kernel<D_IN, HID, true, true><<<dim3(gblk, 1), 256>>>(
        agg1, W1, b1, h1, N, dis, agg2);

    // 5. conv2 aggregation (feature space h=128)
    scatter2_kernel<<<(E * 32 + T - 1) / T, T>>>(h1, row, col, dis, agg2, E);

    // 6. AB = agg2 @ Wf + bf   (h2 and classifier layer1 in one GEMM)
    mma_gemm_kernel<HID, 2 * HID, false, false><<<dim3(gblk, 2), 256>>>(
        agg2, Wf, bf, AB, N, nullptr, nullptr);

    // 7. per-query: relu(A[src]+B[dst]) . Wc2 + bc2
    predict_kernel<<<(Q * 32 + T - 1) / T, T>>>(
        AB, src, dst, Wc2, bc2, out, Q);
}